// round 1
// baseline (speedup 1.0000x reference)
#include <cuda_runtime.h>

#define CC   256   // channels
#define BSZ  32    // batch segments
#define CR   64    // C / R

// Scratch (allocation-free rule: __device__ globals)
__device__ float g_pooled[BSZ * CC];
__device__ float g_counts[BSZ];
__device__ float g_se[BSZ * CC];
__device__ int   g_i64;   // 1 if bidx is int64, 0 if int32

__device__ __forceinline__ int load_seg(const void* __restrict__ bidx, int r, int f64) {
    if (f64) return (int)((const long long* __restrict__)bidx)[r];
    return ((const int* __restrict__)bidx)[r];
}

// ---------------------------------------------------------------------------
// Init: detect bidx dtype + zero accumulators. <<<32, 256>>>
// ---------------------------------------------------------------------------
__global__ void init_kernel(const void* __restrict__ bidx, int N) {
    if (blockIdx.x == 0 && threadIdx.x == 0) {
        // int64 layout: element N/2-1 is a real segment id in [0,32) -> < 64.
        // int32 layout aliased as int64: value = lo + (hi << 32), hi = bidx[N-1]
        // which is >= 1 with overwhelming probability -> huge. (If hi == 0 the
        // whole array is 0 and both interpretations agree anyway.)
        unsigned long long v = ((const unsigned long long*)bidx)[N / 2 - 1];
        g_i64 = (v < 64ull) ? 1 : 0;
    }
    int idx = blockIdx.x * blockDim.x + threadIdx.x;
    if (idx < BSZ * CC) g_pooled[idx] = 0.f;
    if (idx < BSZ)      g_counts[idx] = 0.f;
}

// ---------------------------------------------------------------------------
// Pool: segment sums over sorted bidx. Register accumulation, atomic flush
// only at segment boundaries. 4 row-lanes x 64 float4 col-groups per block.
// ---------------------------------------------------------------------------
__global__ void pool_kernel(const float4* __restrict__ feats,
                            const void* __restrict__ bidx, int N) {
    const int f64 = g_i64;
    const int rpb = (N + gridDim.x - 1) / gridDim.x;
    const int r0 = blockIdx.x * rpb;
    const int r1 = min(r0 + rpb, N);
    const int lane = threadIdx.x >> 6;   // 0..3 row-lane
    const int cg   = threadIdx.x & 63;   // float4 column group

    float4 acc = make_float4(0.f, 0.f, 0.f, 0.f);
    int cur = -1, cnt = 0;

    for (int r = r0 + lane; r < r1; r += 4) {
        int seg = load_seg(bidx, r, f64);
        if (seg != cur) {
            if (cur >= 0) {
                float* p = &g_pooled[cur * CC + cg * 4];
                atomicAdd(p + 0, acc.x); atomicAdd(p + 1, acc.y);
                atomicAdd(p + 2, acc.z); atomicAdd(p + 3, acc.w);
                if (cg == 0) atomicAdd(&g_counts[cur], (float)cnt);
            }
            acc = make_float4(0.f, 0.f, 0.f, 0.f);
            cnt = 0;
            cur = seg;
        }
        float4 v = feats[(long long)r * 64 + cg];
        acc.x += v.x; acc.y += v.y; acc.z += v.z; acc.w += v.w;
        cnt++;
    }
    if (cur >= 0) {
        float* p = &g_pooled[cur * CC + cg * 4];
        atomicAdd(p + 0, acc.x); atomicAdd(p + 1, acc.y);
        atomicAdd(p + 2, acc.z); atomicAdd(p + 3, acc.w);
        if (cg == 0) atomicAdd(&g_counts[cur], (float)cnt);
    }
}

// ---------------------------------------------------------------------------
// MLP: per-segment squeeze-excite. One block per batch index. <<<32, 256>>>
// ---------------------------------------------------------------------------
__global__ void mlp_kernel(const float* __restrict__ fc1_w,
                           const float* __restrict__ fc1_b,
                           const float* __restrict__ fc2_w,
                           const float* __restrict__ fc2_b) {
    __shared__ float sp[CC];
    __shared__ float sh[CR];
    const int b = blockIdx.x;
    const int t = threadIdx.x;

    float inv = 1.f / fmaxf(g_counts[b], 1.f);
    sp[t] = g_pooled[b * CC + t] * inv;
    __syncthreads();

    if (t < CR) {
        float a = fc1_b[t];
        const float* w = &fc1_w[t * CC];
        #pragma unroll 8
        for (int c = 0; c < CC; c++) a = fmaf(sp[c], w[c], a);
        sh[t] = fmaxf(a, 0.f);
    }
    __syncthreads();

    float a = fc2_b[t];
    const float* w = &fc2_w[t * CR];
    #pragma unroll
    for (int j = 0; j < CR; j++) a = fmaf(sh[j], w[j], a);
    g_se[b * CC + t] = 1.f / (1.f + expf(-a));
}

// ---------------------------------------------------------------------------
// Scale: out[i,:] = feats[i,:] * se[bidx[i],:]. float4 streaming.
// ---------------------------------------------------------------------------
__global__ void scale_kernel(const float4* __restrict__ feats,
                             const void* __restrict__ bidx,
                             float4* __restrict__ out, int N) {
    const int f64 = g_i64;
    long long gid = (long long)blockIdx.x * blockDim.x + threadIdx.x;
    long long total = (long long)N * 64;
    if (gid >= total) return;
    int r  = (int)(gid >> 6);
    int cg = (int)(gid & 63);
    int seg = load_seg(bidx, r, f64);
    const float4* se4 = (const float4*)g_se;
    float4 s = se4[seg * 64 + cg];
    float4 v = feats[gid];
    out[gid] = make_float4(v.x * s.x, v.y * s.y, v.z * s.z, v.w * s.w);
}

// ---------------------------------------------------------------------------
extern "C" void kernel_launch(void* const* d_in, const int* in_sizes, int n_in,
                              void* d_out, int out_size) {
    const float* feats = (const float*)d_in[0];
    const float* fc1_w = (const float*)d_in[1];
    const float* fc1_b = (const float*)d_in[2];
    const float* fc2_w = (const float*)d_in[3];
    const float* fc2_b = (const float*)d_in[4];
    const void*  bidx  = d_in[5];
    // d_in[6] = batch_size (hardcoded BSZ=32)

    const int N = in_sizes[0] / CC;

    init_kernel<<<32, 256>>>(bidx, N);
    pool_kernel<<<2048, 256>>>((const float4*)feats, bidx, N);
    mlp_kernel<<<BSZ, 256>>>(fc1_w, fc1_b, fc2_w, fc2_b);

    long long total = (long long)N * 64;
    int blocks = (int)((total + 255) / 256);
    scale_kernel<<<blocks, 256>>>((const float4*)feats, bidx, (float4*)d_out, N);
}